// round 4
// baseline (speedup 1.0000x reference)
#include <cuda_runtime.h>
#include <cstdint>

// TinyRNN: B=4096, T=2048, I=1, H=12, O=2
// 2 lanes/batch; lane k owns rows {6k..6k+5} as 3 f32x2 row-pairs.
// 16 batches/warp, 64-thread CTAs (32 batches), grid=128 -> 256 warps on 128 SMs.
// State r[m] = rcp(exp(2 s_m)+1) (h = 1-2r), weights pre-folded by -2*2log2(e).
// Exchange: 6x shfl.xor(1) of partner's r scalars; broadcast pairs via mov.b64.

#define T_TOTAL 2048
#define NCHUNK  32
#define CH      64
#define XSTRIDE 68   // 64 + 4 pad (16B-aligned rows for cp.async)

__device__ __forceinline__ uint64_t pack2(float lo, float hi) {
    uint64_t r; asm("mov.b64 %0, {%1, %2};" : "=l"(r) : "f"(lo), "f"(hi)); return r;
}
__device__ __forceinline__ void unpack2(uint64_t v, float &lo, float &hi) {
    asm("mov.b64 {%0, %1}, %2;" : "=f"(lo), "=f"(hi) : "l"(v));
}
__device__ __forceinline__ uint64_t mul2(uint64_t a, uint64_t b) {
    uint64_t r; asm("mul.rn.f32x2 %0, %1, %2;" : "=l"(r) : "l"(a), "l"(b)); return r;
}
__device__ __forceinline__ uint64_t fma2(uint64_t a, uint64_t b, uint64_t c) {
    uint64_t r; asm("fma.rn.f32x2 %0, %1, %2, %3;" : "=l"(r) : "l"(a), "l"(b), "l"(c)); return r;
}
__device__ __forceinline__ uint64_t add2(uint64_t a, uint64_t b) {
    uint64_t r; asm("add.rn.f32x2 %0, %1, %2;" : "=l"(r) : "l"(a), "l"(b)); return r;
}
__device__ __forceinline__ float ex2f(float x) {
    float r; asm("ex2.approx.f32 %0, %1;" : "=f"(r) : "f"(x)); return r;
}
__device__ __forceinline__ float rcpf(float x) {
    float r; asm("rcp.approx.f32 %0, %1;" : "=f"(r) : "f"(x)); return r;
}

__global__ void __launch_bounds__(64, 1) tinyrnn_kernel(
    const float* __restrict__ x,       // [4096, 2048, 1]
    const float* __restrict__ W_ih,    // [12, 1]
    const float* __restrict__ W_hh,    // [12, 12]
    const float* __restrict__ b_ih,    // [12]
    const float* __restrict__ b_hh,    // [12]
    const float* __restrict__ W_head,  // [2, 12]
    const float* __restrict__ b_head,  // [2]
    float* __restrict__ out)           // [4096, 2]
{
    __shared__ float sx[2][32 * XSTRIDE];

    const int tid  = threadIdx.x;           // 0..63
    const int k    = tid & 1;               // lane within batch pair
    const int bic  = tid >> 1;              // batch in CTA (0..31)
    const int batch = blockIdx.x * 32 + bic;

    const float C2 = 2.885390081777927f;    // 2*log2(e)
    const float KN = -2.0f * C2;

    // --- fold weights: lane owns row-pairs (6k+2j, 6k+2j+1), j=0..2 ---
    // Wo[j][i]: column m = 6k+i (own r's); Wq[j][i]: column m = 6(1-k)+i (partner)
    uint64_t Wo[3][6], Wq[3][6];
    uint64_t Ap[3], Bxp[3];
    const int mo = 6 * k, mp = 6 * (1 - k);
#pragma unroll
    for (int j = 0; j < 3; j++) {
        const int p0 = 6 * k + 2 * j, p1 = p0 + 1;
        float s0 = 0.0f, s1 = 0.0f;
#pragma unroll
        for (int m = 0; m < 12; m++) { s0 += W_hh[p0 * 12 + m]; s1 += W_hh[p1 * 12 + m]; }
#pragma unroll
        for (int i = 0; i < 6; i++) {
            Wo[j][i] = pack2(KN * W_hh[p0 * 12 + mo + i], KN * W_hh[p1 * 12 + mo + i]);
            Wq[j][i] = pack2(KN * W_hh[p0 * 12 + mp + i], KN * W_hh[p1 * 12 + mp + i]);
        }
        Ap[j]  = pack2(C2 * (b_ih[p0] + b_hh[p0] + s0), C2 * (b_ih[p1] + b_hh[p1] + s1));
        Bxp[j] = pack2(C2 * W_ih[p0], C2 * W_ih[p1]);
    }

    const float* xcta = x + (size_t)blockIdx.x * 32 * T_TOTAL;

    // --- cp.async chunk prefetch: 32 batches x 64 steps = 512 float4 ---
    auto prefetch = [&](int c, int buf) {
#pragma unroll
        for (int rr = 0; rr < 8; rr++) {
            int flat = rr * 64 + tid;       // 0..511
            int b    = flat >> 4;
            int q    = flat & 15;
            const float* src = xcta + (size_t)b * T_TOTAL + c * CH + q * 4;
            unsigned dst = (unsigned)__cvta_generic_to_shared(
                &sx[buf][b * XSTRIDE + q * 4]);
            asm volatile("cp.async.ca.shared.global [%0], [%1], 16;\n"
                         :: "r"(dst), "l"(src));
        }
        asm volatile("cp.async.commit_group;\n");
    };

    prefetch(0, 0);

    // state: r for own 6 rows; h=0 -> r=0.5
    float r[6];
#pragma unroll
    for (int i = 0; i < 6; i++) r[i] = 0.5f;

    for (int c = 0; c < NCHUNK; c++) {
        const int cur = c & 1;
        if (c + 1 < NCHUNK) {
            prefetch(c + 1, cur ^ 1);
            asm volatile("cp.async.wait_group 1;\n");
        } else {
            asm volatile("cp.async.wait_group 0;\n");
        }
        __syncthreads();

        const float* xs = &sx[cur][bic * XSTRIDE];

#pragma unroll 2
        for (int tt = 0; tt < CH; tt++) {
            const float xt = xs[tt];
            const uint64_t xp = pack2(xt, xt);

            // exchange: partner's 6 r scalars (lane^1)
            float q0 = __shfl_xor_sync(0xffffffffu, r[0], 1, 2);
            float q1 = __shfl_xor_sync(0xffffffffu, r[1], 1, 2);
            float q2 = __shfl_xor_sync(0xffffffffu, r[2], 1, 2);
            float q3 = __shfl_xor_sync(0xffffffffu, r[3], 1, 2);
            float q4 = __shfl_xor_sync(0xffffffffu, r[4], 1, 2);
            float q5 = __shfl_xor_sync(0xffffffffu, r[5], 1, 2);

            // broadcast pairs
            uint64_t po[6], pq[6];
            po[0] = pack2(r[0], r[0]); po[1] = pack2(r[1], r[1]);
            po[2] = pack2(r[2], r[2]); po[3] = pack2(r[3], r[3]);
            po[4] = pack2(r[4], r[4]); po[5] = pack2(r[5], r[5]);
            pq[0] = pack2(q0, q0); pq[1] = pack2(q1, q1);
            pq[2] = pack2(q2, q2); pq[3] = pack2(q3, q3);
            pq[4] = pack2(q4, q4); pq[5] = pack2(q5, q5);

#pragma unroll
            for (int j = 0; j < 3; j++) {
                const uint64_t u = fma2(xp, Bxp[j], Ap[j]);
                // two 6-deep chains
                uint64_t a = fma2(Wo[j][0], po[0], u);
                uint64_t b = mul2(Wo[j][1], po[1]);
                a = fma2(Wo[j][2], po[2], a);
                b = fma2(Wo[j][3], po[3], b);
                a = fma2(Wo[j][4], po[4], a);
                b = fma2(Wo[j][5], po[5], b);
                a = fma2(Wq[j][0], pq[0], a);
                b = fma2(Wq[j][1], pq[1], b);
                a = fma2(Wq[j][2], pq[2], a);
                b = fma2(Wq[j][3], pq[3], b);
                a = fma2(Wq[j][4], pq[4], a);
                b = fma2(Wq[j][5], pq[5], b);
                float slo, shi;
                unpack2(add2(a, b), slo, shi);
                r[2 * j + 0] = rcpf(ex2f(slo) + 1.0f);
                r[2 * j + 1] = rcpf(ex2f(shi) + 1.0f);
            }
        }
        __syncthreads();
    }

    // --- head: h[m] = 1 - 2 r[m] ---
    float other[6];
#pragma unroll
    for (int i = 0; i < 6; i++)
        other[i] = __shfl_xor_sync(0xffffffffu, r[i], 1, 2);

    if (k == 0) {
        float g[12];
#pragma unroll
        for (int i = 0; i < 6; i++) { g[i] = r[i]; g[6 + i] = other[i]; }
        float o0 = b_head[0];
        float o1 = b_head[1];
#pragma unroll
        for (int m = 0; m < 12; m++) {
            float h = fmaf(-2.0f, g[m], 1.0f);
            o0 = fmaf(W_head[m],      h, o0);
            o1 = fmaf(W_head[12 + m], h, o1);
        }
        out[batch * 2 + 0] = o0;
        out[batch * 2 + 1] = o1;
    }
}

extern "C" void kernel_launch(void* const* d_in, const int* in_sizes, int n_in,
                              void* d_out, int out_size)
{
    const float* x      = (const float*)d_in[0];
    const float* W_ih   = (const float*)d_in[1];
    const float* W_hh   = (const float*)d_in[2];
    const float* b_ih   = (const float*)d_in[3];
    const float* b_hh   = (const float*)d_in[4];
    const float* W_head = (const float*)d_in[5];
    const float* b_head = (const float*)d_in[6];
    float* out = (float*)d_out;

    tinyrnn_kernel<<<128, 64>>>(x, W_ih, W_hh, b_ih, b_hh, W_head, b_head, out);
}

// round 5
// speedup vs baseline: 1.4657x; 1.4657x over previous
#include <cuda_runtime.h>
#include <cstdint>

// TinyRNN: B=4096, T=2048, I=1, H=12, O=2
// 2 lanes/batch; lane k owns rows {6k..6k+5} as 3 f32x2 row-pairs.
// 16 batches/warp, 64-thread CTAs (32 batches), grid=128 -> 256 warps.
// tanh via MUFU.TANH (tanh.approx.f32): 6 MUFU/lane-step, chain seg 16 cyc.
// Exchange: 6x shfl.xor(1) of partner h scalars.

#define T_TOTAL 2048
#define NCHUNK  32
#define CH      64
#define XSTRIDE 68   // 64 + 4 pad (16B-aligned rows for cp.async)

__device__ __forceinline__ uint64_t pack2(float lo, float hi) {
    uint64_t r; asm("mov.b64 %0, {%1, %2};" : "=l"(r) : "f"(lo), "f"(hi)); return r;
}
__device__ __forceinline__ void unpack2(uint64_t v, float &lo, float &hi) {
    asm("mov.b64 {%0, %1}, %2;" : "=f"(lo), "=f"(hi) : "l"(v));
}
__device__ __forceinline__ uint64_t mul2(uint64_t a, uint64_t b) {
    uint64_t r; asm("mul.rn.f32x2 %0, %1, %2;" : "=l"(r) : "l"(a), "l"(b)); return r;
}
__device__ __forceinline__ uint64_t fma2(uint64_t a, uint64_t b, uint64_t c) {
    uint64_t r; asm("fma.rn.f32x2 %0, %1, %2, %3;" : "=l"(r) : "l"(a), "l"(b), "l"(c)); return r;
}
__device__ __forceinline__ uint64_t add2(uint64_t a, uint64_t b) {
    uint64_t r; asm("add.rn.f32x2 %0, %1, %2;" : "=l"(r) : "l"(a), "l"(b)); return r;
}
__device__ __forceinline__ float tanhf_hw(float x) {
    float r; asm("tanh.approx.f32 %0, %1;" : "=f"(r) : "f"(x)); return r;
}

__global__ void __launch_bounds__(64, 1) tinyrnn_kernel(
    const float* __restrict__ x,       // [4096, 2048, 1]
    const float* __restrict__ W_ih,    // [12, 1]
    const float* __restrict__ W_hh,    // [12, 12]
    const float* __restrict__ b_ih,    // [12]
    const float* __restrict__ b_hh,    // [12]
    const float* __restrict__ W_head,  // [2, 12]
    const float* __restrict__ b_head,  // [2]
    float* __restrict__ out)           // [4096, 2]
{
    __shared__ float sx[2][32 * XSTRIDE];

    const int tid  = threadIdx.x;           // 0..63
    const int k    = tid & 1;               // lane within batch pair
    const int bic  = tid >> 1;              // batch in CTA (0..31)
    const int batch = blockIdx.x * 32 + bic;

    // --- weights: lane owns row-pairs (6k+2j, 6k+2j+1), j=0..2 ---
    // Wo[j][i]: multiplies own h[6k+i]; Wq[j][i]: partner h[6(1-k)+i]
    uint64_t Wo[3][6], Wq[3][6];
    uint64_t Ap[3], Bxp[3];
    const int mo = 6 * k, mp = 6 * (1 - k);
#pragma unroll
    for (int j = 0; j < 3; j++) {
        const int p0 = 6 * k + 2 * j, p1 = p0 + 1;
#pragma unroll
        for (int i = 0; i < 6; i++) {
            Wo[j][i] = pack2(W_hh[p0 * 12 + mo + i], W_hh[p1 * 12 + mo + i]);
            Wq[j][i] = pack2(W_hh[p0 * 12 + mp + i], W_hh[p1 * 12 + mp + i]);
        }
        Ap[j]  = pack2(b_ih[p0] + b_hh[p0], b_ih[p1] + b_hh[p1]);
        Bxp[j] = pack2(W_ih[p0], W_ih[p1]);
    }

    const float* xcta = x + (size_t)blockIdx.x * 32 * T_TOTAL;

    // --- cp.async chunk prefetch: 32 batches x 64 steps = 512 float4 ---
    auto prefetch = [&](int c, int buf) {
#pragma unroll
        for (int rr = 0; rr < 8; rr++) {
            int flat = rr * 64 + tid;       // 0..511
            int b    = flat >> 4;
            int q    = flat & 15;
            const float* src = xcta + (size_t)b * T_TOTAL + c * CH + q * 4;
            unsigned dst = (unsigned)__cvta_generic_to_shared(
                &sx[buf][b * XSTRIDE + q * 4]);
            asm volatile("cp.async.ca.shared.global [%0], [%1], 16;\n"
                         :: "r"(dst), "l"(src));
        }
        asm volatile("cp.async.commit_group;\n");
    };

    prefetch(0, 0);

    // state: own 6 h values (h0 = 0)
    float h[6];
#pragma unroll
    for (int i = 0; i < 6; i++) h[i] = 0.0f;

    for (int c = 0; c < NCHUNK; c++) {
        const int cur = c & 1;
        if (c + 1 < NCHUNK) {
            prefetch(c + 1, cur ^ 1);
            asm volatile("cp.async.wait_group 1;\n");
        } else {
            asm volatile("cp.async.wait_group 0;\n");
        }
        __syncthreads();

        const float* xs = &sx[cur][bic * XSTRIDE];

#pragma unroll 2
        for (int tt = 0; tt < CH; tt++) {
            const float xt = xs[tt];
            const uint64_t xp = pack2(xt, xt);

            // exchange partner's 6 h scalars (off fma pipe; overlaps broadcasts)
            const float q0 = __shfl_xor_sync(0xffffffffu, h[0], 1, 2);
            const float q1 = __shfl_xor_sync(0xffffffffu, h[1], 1, 2);
            const float q2 = __shfl_xor_sync(0xffffffffu, h[2], 1, 2);
            const float q3 = __shfl_xor_sync(0xffffffffu, h[3], 1, 2);
            const float q4 = __shfl_xor_sync(0xffffffffu, h[4], 1, 2);
            const float q5 = __shfl_xor_sync(0xffffffffu, h[5], 1, 2);

            // broadcast pairs (own h available right after tanh; partner after shfl)
            uint64_t po[6], pq[6];
            po[0] = pack2(h[0], h[0]); po[1] = pack2(h[1], h[1]);
            po[2] = pack2(h[2], h[2]); po[3] = pack2(h[3], h[3]);
            po[4] = pack2(h[4], h[4]); po[5] = pack2(h[5], h[5]);
            pq[0] = pack2(q0, q0); pq[1] = pack2(q1, q1);
            pq[2] = pack2(q2, q2); pq[3] = pack2(q3, q3);
            pq[4] = pack2(q4, q4); pq[5] = pack2(q5, q5);

#pragma unroll
            for (int j = 0; j < 3; j++) {
                // chain a: u + own terms (ready first); chain b: rest
                uint64_t a = fma2(xp, Bxp[j], Ap[j]);
                a = fma2(Wo[j][0], po[0], a);
                uint64_t b = mul2(Wo[j][1], po[1]);
                a = fma2(Wo[j][2], po[2], a);
                b = fma2(Wo[j][3], po[3], b);
                a = fma2(Wo[j][4], po[4], a);
                b = fma2(Wo[j][5], po[5], b);
                a = fma2(Wq[j][0], pq[0], a);
                b = fma2(Wq[j][1], pq[1], b);
                a = fma2(Wq[j][2], pq[2], a);
                b = fma2(Wq[j][3], pq[3], b);
                a = fma2(Wq[j][4], pq[4], a);
                b = fma2(Wq[j][5], pq[5], b);
                float slo, shi;
                unpack2(add2(a, b), slo, shi);
                h[2 * j + 0] = tanhf_hw(slo);
                h[2 * j + 1] = tanhf_hw(shi);
            }
        }
        __syncthreads();
    }

    // --- head ---
    float other[6];
#pragma unroll
    for (int i = 0; i < 6; i++)
        other[i] = __shfl_xor_sync(0xffffffffu, h[i], 1, 2);

    if (k == 0) {
        float g[12];
#pragma unroll
        for (int i = 0; i < 6; i++) { g[i] = h[i]; g[6 + i] = other[i]; }
        float o0 = b_head[0];
        float o1 = b_head[1];
#pragma unroll
        for (int m = 0; m < 12; m++) {
            o0 = fmaf(W_head[m],      g[m], o0);
            o1 = fmaf(W_head[12 + m], g[m], o1);
        }
        out[batch * 2 + 0] = o0;
        out[batch * 2 + 1] = o1;
    }
}

extern "C" void kernel_launch(void* const* d_in, const int* in_sizes, int n_in,
                              void* d_out, int out_size)
{
    const float* x      = (const float*)d_in[0];
    const float* W_ih   = (const float*)d_in[1];
    const float* W_hh   = (const float*)d_in[2];
    const float* b_ih   = (const float*)d_in[3];
    const float* b_hh   = (const float*)d_in[4];
    const float* W_head = (const float*)d_in[5];
    const float* b_head = (const float*)d_in[6];
    float* out = (float*)d_out;

    tinyrnn_kernel<<<128, 64>>>(x, W_ih, W_hh, b_ih, b_hh, W_head, b_head, out);
}

// round 6
// speedup vs baseline: 1.8487x; 1.2613x over previous
#include <cuda_runtime.h>
#include <cstdint>

// TinyRNN: B=4096, T=2048, I=1, H=12, O=2
// 4 lanes/batch; lane k owns rows {3k..3k+2}; 8 batches/warp;
// 128-thread CTAs (32 batches), grid=128 -> 512 warps (1/SMSP on 128 SMs).
// Column-pair f32x2 packing in LOCAL order (own cols first, then xor-partners),
// weights gathered at init to match. Exchange: 9x shfl.xor. tanh via MUFU.TANH.

#define T_TOTAL 2048
#define NCHUNK  32
#define CH      64
#define XSTRIDE 68   // 64 + 4 pad

__device__ __forceinline__ uint64_t pack2(float lo, float hi) {
    uint64_t r; asm("mov.b64 %0, {%1, %2};" : "=l"(r) : "f"(lo), "f"(hi)); return r;
}
__device__ __forceinline__ void unpack2(uint64_t v, float &lo, float &hi) {
    asm("mov.b64 {%0, %1}, %2;" : "=f"(lo), "=f"(hi) : "l"(v));
}
__device__ __forceinline__ uint64_t mul2(uint64_t a, uint64_t b) {
    uint64_t r; asm("mul.rn.f32x2 %0, %1, %2;" : "=l"(r) : "l"(a), "l"(b)); return r;
}
__device__ __forceinline__ uint64_t fma2(uint64_t a, uint64_t b, uint64_t c) {
    uint64_t r; asm("fma.rn.f32x2 %0, %1, %2, %3;" : "=l"(r) : "l"(a), "l"(b), "l"(c)); return r;
}
__device__ __forceinline__ uint64_t add2(uint64_t a, uint64_t b) {
    uint64_t r; asm("add.rn.f32x2 %0, %1, %2;" : "=l"(r) : "l"(a), "l"(b)); return r;
}
__device__ __forceinline__ float tanhf_hw(float x) {
    float r; asm("tanh.approx.f32 %0, %1;" : "=f"(r) : "f"(x)); return r;
}

__global__ void __launch_bounds__(128, 1) tinyrnn_kernel(
    const float* __restrict__ x,       // [4096, 2048, 1]
    const float* __restrict__ W_ih,    // [12, 1]
    const float* __restrict__ W_hh,    // [12, 12]
    const float* __restrict__ b_ih,    // [12]
    const float* __restrict__ b_hh,    // [12]
    const float* __restrict__ W_head,  // [2, 12]
    const float* __restrict__ b_head,  // [2]
    float* __restrict__ out)           // [4096, 2]
{
    __shared__ float sx[2][32 * XSTRIDE];

    const int tid  = threadIdx.x;
    const int lane = tid & 31;
    const int warp = tid >> 5;
    const int k    = lane & 3;              // lane within 4-lane group
    const int wb   = lane >> 2;             // batch within warp (0..7)
    const int bic  = warp * 8 + wb;         // batch in CTA (0..31)
    const int batch = blockIdx.x * 32 + bic;

    // local column order: c[3d+i] = 3*(k^d)+i  (d=0 self, then xor partners)
    int cidx[12];
#pragma unroll
    for (int d = 0; d < 4; d++) {
        const int p = k ^ d;
#pragma unroll
        for (int i = 0; i < 3; i++) cidx[3 * d + i] = 3 * p + i;
    }

    // weights per owned row r=3k+i, packed per local column pair
    uint64_t Wc[3][6];
    float A[3], Bx[3];
#pragma unroll
    for (int i = 0; i < 3; i++) {
        const int r = 3 * k + i;
#pragma unroll
        for (int j = 0; j < 6; j++)
            Wc[i][j] = pack2(W_hh[r * 12 + cidx[2 * j]],
                             W_hh[r * 12 + cidx[2 * j + 1]]);
        A[i]  = b_ih[r] + b_hh[r];
        Bx[i] = W_ih[r];
    }

    const float* xcta = x + (size_t)blockIdx.x * 32 * T_TOTAL;

    // --- cp.async chunk prefetch: 32 batches x 64 steps = 512 float4 ---
    auto prefetch = [&](int c, int buf) {
#pragma unroll
        for (int rr = 0; rr < 4; rr++) {
            int flat = rr * 128 + tid;      // 0..511
            int b    = flat >> 4;
            int q    = flat & 15;
            const float* src = xcta + (size_t)b * T_TOTAL + c * CH + q * 4;
            unsigned dst = (unsigned)__cvta_generic_to_shared(
                &sx[buf][b * XSTRIDE + q * 4]);
            asm volatile("cp.async.ca.shared.global [%0], [%1], 16;\n"
                         :: "r"(dst), "l"(src));
        }
        asm volatile("cp.async.commit_group;\n");
    };

    prefetch(0, 0);

    float h0 = 0.0f, h1 = 0.0f, h2 = 0.0f;  // own rows 3k..3k+2

    for (int c = 0; c < NCHUNK; c++) {
        const int cur = c & 1;
        if (c + 1 < NCHUNK) {
            prefetch(c + 1, cur ^ 1);
            asm volatile("cp.async.wait_group 1;\n");
        } else {
            asm volatile("cp.async.wait_group 0;\n");
        }
        __syncthreads();

        const float* xs = &sx[cur][bic * XSTRIDE];

#pragma unroll 2
        for (int tt = 0; tt < CH; tt++) {
            const float xt = xs[tt];
            // bias/x terms, off the serial chain
            const float u0 = fmaf(xt, Bx[0], A[0]);
            const float u1 = fmaf(xt, Bx[1], A[1]);
            const float u2 = fmaf(xt, Bx[2], A[2]);

            // exchange: 9 shfl.xor -> g in LOCAL order (g0..2 own)
            const float g3 = __shfl_xor_sync(0xffffffffu, h0, 1, 4);
            const float g4 = __shfl_xor_sync(0xffffffffu, h1, 1, 4);
            const float g5 = __shfl_xor_sync(0xffffffffu, h2, 1, 4);
            const float g6 = __shfl_xor_sync(0xffffffffu, h0, 2, 4);
            const float g7 = __shfl_xor_sync(0xffffffffu, h1, 2, 4);
            const float g8 = __shfl_xor_sync(0xffffffffu, h2, 2, 4);
            const float g9 = __shfl_xor_sync(0xffffffffu, h0, 3, 4);
            const float ga = __shfl_xor_sync(0xffffffffu, h1, 3, 4);
            const float gb = __shfl_xor_sync(0xffffffffu, h2, 3, 4);

            // 6 column pairs (local order)
            const uint64_t P0 = pack2(h0, h1);   // own, ready early
            const uint64_t P1 = pack2(h2, g3);
            const uint64_t P2 = pack2(g4, g5);
            const uint64_t P3 = pack2(g6, g7);
            const uint64_t P4 = pack2(g8, g9);
            const uint64_t P5 = pack2(ga, gb);

            const float uu[3] = {u0, u1, u2};
            float hn[3];
#pragma unroll
            for (int i = 0; i < 3; i++) {
                uint64_t aA = fma2(Wc[i][0], P0, pack2(uu[i], 0.0f));
                uint64_t aB = mul2(Wc[i][1], P1);
                aA = fma2(Wc[i][2], P2, aA);
                aB = fma2(Wc[i][3], P3, aB);
                aA = fma2(Wc[i][4], P4, aA);
                aB = fma2(Wc[i][5], P5, aB);
                float lo, hi;
                unpack2(add2(aA, aB), lo, hi);
                hn[i] = tanhf_hw(lo + hi);
            }
            h0 = hn[0]; h1 = hn[1]; h2 = hn[2];
        }
        __syncthreads();
    }

    // --- head: rebuild full h; for k==0 local order == global order ---
    float g[12];
    g[0] = h0; g[1] = h1; g[2] = h2;
    g[3] = __shfl_xor_sync(0xffffffffu, h0, 1, 4);
    g[4] = __shfl_xor_sync(0xffffffffu, h1, 1, 4);
    g[5] = __shfl_xor_sync(0xffffffffu, h2, 1, 4);
    g[6] = __shfl_xor_sync(0xffffffffu, h0, 2, 4);
    g[7] = __shfl_xor_sync(0xffffffffu, h1, 2, 4);
    g[8] = __shfl_xor_sync(0xffffffffu, h2, 2, 4);
    g[9] = __shfl_xor_sync(0xffffffffu, h0, 3, 4);
    g[10] = __shfl_xor_sync(0xffffffffu, h1, 3, 4);
    g[11] = __shfl_xor_sync(0xffffffffu, h2, 3, 4);

    if (k == 0) {
        float o0 = b_head[0];
        float o1 = b_head[1];
#pragma unroll
        for (int m = 0; m < 12; m++) {
            o0 = fmaf(W_head[m],      g[m], o0);
            o1 = fmaf(W_head[12 + m], g[m], o1);
        }
        out[batch * 2 + 0] = o0;
        out[batch * 2 + 1] = o1;
    }
}

extern "C" void kernel_launch(void* const* d_in, const int* in_sizes, int n_in,
                              void* d_out, int out_size)
{
    const float* x      = (const float*)d_in[0];
    const float* W_ih   = (const float*)d_in[1];
    const float* W_hh   = (const float*)d_in[2];
    const float* b_ih   = (const float*)d_in[3];
    const float* b_hh   = (const float*)d_in[4];
    const float* W_head = (const float*)d_in[5];
    const float* b_head = (const float*)d_in[6];
    float* out = (float*)d_out;

    tinyrnn_kernel<<<128, 128>>>(x, W_ih, W_hh, b_ih, b_hh, W_head, b_head, out);
}

// round 7
// speedup vs baseline: 1.9237x; 1.0405x over previous
#include <cuda_runtime.h>
#include <cstdint>

// TinyRNN: B=4096, T=2048, I=1, H=12, O=2
// 4 lanes/batch; lane k owns rows {3k..3k+2}; 8 batches/warp;
// 128-thread CTAs (32 batches), grid=128 -> 512 warps (1/SMSP on 128 SMs).
// Exchange: 9x shfl.xor. tanh via MUFU.TANH.
// Tree: 4 packed (h0,h1)-column pairs per direction; the 4 late h2-columns
// enter via a flat scalar FFMA tail ordered by shfl arrival, so post-last-
// operand depth is ffma+tanh only.

#define T_TOTAL 2048
#define NCHUNK  32
#define CH      64
#define XSTRIDE 68   // 64 + 4 pad

__device__ __forceinline__ uint64_t pack2(float lo, float hi) {
    uint64_t r; asm("mov.b64 %0, {%1, %2};" : "=l"(r) : "f"(lo), "f"(hi)); return r;
}
__device__ __forceinline__ void unpack2(uint64_t v, float &lo, float &hi) {
    asm("mov.b64 {%0, %1}, %2;" : "=f"(lo), "=f"(hi) : "l"(v));
}
__device__ __forceinline__ uint64_t mul2(uint64_t a, uint64_t b) {
    uint64_t r; asm("mul.rn.f32x2 %0, %1, %2;" : "=l"(r) : "l"(a), "l"(b)); return r;
}
__device__ __forceinline__ uint64_t fma2(uint64_t a, uint64_t b, uint64_t c) {
    uint64_t r; asm("fma.rn.f32x2 %0, %1, %2, %3;" : "=l"(r) : "l"(a), "l"(b), "l"(c)); return r;
}
__device__ __forceinline__ uint64_t add2(uint64_t a, uint64_t b) {
    uint64_t r; asm("add.rn.f32x2 %0, %1, %2;" : "=l"(r) : "l"(a), "l"(b)); return r;
}
__device__ __forceinline__ float tanhf_hw(float x) {
    float r; asm("tanh.approx.f32 %0, %1;" : "=f"(r) : "f"(x)); return r;
}

__global__ void __launch_bounds__(128, 1) tinyrnn_kernel(
    const float* __restrict__ x,       // [4096, 2048, 1]
    const float* __restrict__ W_ih,    // [12, 1]
    const float* __restrict__ W_hh,    // [12, 12]
    const float* __restrict__ b_ih,    // [12]
    const float* __restrict__ b_hh,    // [12]
    const float* __restrict__ W_head,  // [2, 12]
    const float* __restrict__ b_head,  // [2]
    float* __restrict__ out)           // [4096, 2]
{
    __shared__ float sx[2][32 * XSTRIDE];

    const int tid  = threadIdx.x;
    const int lane = tid & 31;
    const int warp = tid >> 5;
    const int k    = lane & 3;              // lane within 4-lane group
    const int wb   = lane >> 2;             // batch within warp (0..7)
    const int bic  = warp * 8 + wb;         // batch in CTA (0..31)
    const int batch = blockIdx.x * 32 + bic;

    // weights per owned row r=3k+i:
    //  Wp[i][d]: packed pair for columns (3(k^d), 3(k^d)+1)   (the h0,h1 of dir d)
    //  ws[i][d]: scalar for column 3(k^d)+2                   (the h2 of dir d)
    uint64_t Wp[3][4];
    float    ws[3][4];
    float A[3], Bx[3];
#pragma unroll
    for (int i = 0; i < 3; i++) {
        const int r = 3 * k + i;
#pragma unroll
        for (int d = 0; d < 4; d++) {
            const int cb = 3 * (k ^ d);
            Wp[i][d] = pack2(W_hh[r * 12 + cb], W_hh[r * 12 + cb + 1]);
            ws[i][d] = W_hh[r * 12 + cb + 2];
        }
        A[i]  = b_ih[r] + b_hh[r];
        Bx[i] = W_ih[r];
    }

    const float* xcta = x + (size_t)blockIdx.x * 32 * T_TOTAL;

    // --- cp.async chunk prefetch: 32 batches x 64 steps = 512 float4 ---
    auto prefetch = [&](int c, int buf) {
#pragma unroll
        for (int rr = 0; rr < 4; rr++) {
            int flat = rr * 128 + tid;      // 0..511
            int b    = flat >> 4;
            int q    = flat & 15;
            const float* src = xcta + (size_t)b * T_TOTAL + c * CH + q * 4;
            unsigned dst = (unsigned)__cvta_generic_to_shared(
                &sx[buf][b * XSTRIDE + q * 4]);
            asm volatile("cp.async.ca.shared.global [%0], [%1], 16;\n"
                         :: "r"(dst), "l"(src));
        }
        asm volatile("cp.async.commit_group;\n");
    };

    prefetch(0, 0);

    float h0 = 0.0f, h1 = 0.0f, h2 = 0.0f;  // own rows 3k..3k+2

    for (int c = 0; c < NCHUNK; c++) {
        const int cur = c & 1;
        if (c + 1 < NCHUNK) {
            prefetch(c + 1, cur ^ 1);
            asm volatile("cp.async.wait_group 1;\n");
        } else {
            asm volatile("cp.async.wait_group 0;\n");
        }
        __syncthreads();

        const float* xs = &sx[cur][bic * XSTRIDE];

#pragma unroll 4
        for (int tt = 0; tt < CH; tt++) {
            const float xt = xs[tt];
            // bias/x init terms, off the serial chain
            const uint64_t U0 = pack2(fmaf(xt, Bx[0], A[0]), 0.0f);
            const uint64_t U1 = pack2(fmaf(xt, Bx[1], A[1]), 0.0f);
            const uint64_t U2 = pack2(fmaf(xt, Bx[2], A[2]), 0.0f);

            // exchange: h0,h1 shfls first (earlier tanh), h2 last
            const float a0 = __shfl_xor_sync(0xffffffffu, h0, 1, 4);
            const float b0 = __shfl_xor_sync(0xffffffffu, h0, 2, 4);
            const float c0 = __shfl_xor_sync(0xffffffffu, h0, 3, 4);
            const float a1 = __shfl_xor_sync(0xffffffffu, h1, 1, 4);
            const float b1 = __shfl_xor_sync(0xffffffffu, h1, 2, 4);
            const float c1 = __shfl_xor_sync(0xffffffffu, h1, 3, 4);
            const float a2 = __shfl_xor_sync(0xffffffffu, h2, 1, 4);
            const float b2 = __shfl_xor_sync(0xffffffffu, h2, 2, 4);
            const float c2 = __shfl_xor_sync(0xffffffffu, h2, 3, 4);

            // packed (h0,h1) pairs per direction
            const uint64_t P0 = pack2(h0, h1);   // own, ready earliest
            const uint64_t P1 = pack2(a0, a1);
            const uint64_t P2 = pack2(b0, b1);
            const uint64_t P3 = pack2(c0, c1);

            float hn[3];
            const uint64_t UU[3] = {U0, U1, U2};
#pragma unroll
            for (int i = 0; i < 3; i++) {
                uint64_t aA = fma2(Wp[i][0], P0, UU[i]);
                uint64_t aB = mul2(Wp[i][1], P1);
                aA = fma2(Wp[i][2], P2, aA);
                aB = fma2(Wp[i][3], P3, aB);
                float lo, hi;
                unpack2(add2(aA, aB), lo, hi);
                float s = lo + hi;
                // flat scalar tail, ordered by arrival: own h2, then d1,d2,d3
                s = fmaf(ws[i][0], h2, s);
                s = fmaf(ws[i][1], a2, s);
                s = fmaf(ws[i][2], b2, s);
                s = fmaf(ws[i][3], c2, s);
                hn[i] = tanhf_hw(s);
            }
            h0 = hn[0]; h1 = hn[1]; h2 = hn[2];
        }
        __syncthreads();
    }

    // --- head: rebuild full h; for k==0 local order == global order ---
    float g[12];
    g[0] = h0; g[1] = h1; g[2] = h2;
    g[3] = __shfl_xor_sync(0xffffffffu, h0, 1, 4);
    g[4] = __shfl_xor_sync(0xffffffffu, h1, 1, 4);
    g[5] = __shfl_xor_sync(0xffffffffu, h2, 1, 4);
    g[6] = __shfl_xor_sync(0xffffffffu, h0, 2, 4);
    g[7] = __shfl_xor_sync(0xffffffffu, h1, 2, 4);
    g[8] = __shfl_xor_sync(0xffffffffu, h2, 2, 4);
    g[9]  = __shfl_xor_sync(0xffffffffu, h0, 3, 4);
    g[10] = __shfl_xor_sync(0xffffffffu, h1, 3, 4);
    g[11] = __shfl_xor_sync(0xffffffffu, h2, 3, 4);

    if (k == 0) {
        float o0 = b_head[0];
        float o1 = b_head[1];
#pragma unroll
        for (int m = 0; m < 12; m++) {
            o0 = fmaf(W_head[m],      g[m], o0);
            o1 = fmaf(W_head[12 + m], g[m], o1);
        }
        out[batch * 2 + 0] = o0;
        out[batch * 2 + 1] = o1;
    }
}

extern "C" void kernel_launch(void* const* d_in, const int* in_sizes, int n_in,
                              void* d_out, int out_size)
{
    const float* x      = (const float*)d_in[0];
    const float* W_ih   = (const float*)d_in[1];
    const float* W_hh   = (const float*)d_in[2];
    const float* b_ih   = (const float*)d_in[3];
    const float* b_hh   = (const float*)d_in[4];
    const float* W_head = (const float*)d_in[5];
    const float* b_head = (const float*)d_in[6];
    float* out = (float*)d_out;

    tinyrnn_kernel<<<128, 128>>>(x, W_ih, W_hh, b_ih, b_hh, W_head, b_head, out);
}